// round 11
// baseline (speedup 1.0000x reference)
#include <cuda_runtime.h>

namespace {

constexpr int kNodes = 50000;
constexpr int kEdges = 800000;
constexpr int kScanBlocks = (kNodes + 255) / 256;  // 196

// Scratch (allocation-free __device__ globals; float4-typed => 16B aligned).
__device__ float4 g_xc[kNodes * 32];   // fp32 normalized caps
__device__ float4 g_u [kNodes * 32];   // routing state (updated in place per node)
__device__ int    g_count [kNodes + 1];
__device__ int    g_incl  [kNodes + 1];
__device__ int    g_bsum  [kScanBlocks];
__device__ int    g_bpre  [kScanBlocks];
__device__ int    g_offs  [kNodes + 1];  // CSR row offsets (by target)
__device__ int    g_cursor[kNodes];
__device__ int    g_srcs  [kEdges];      // CSR column (source node per edge)
__device__ int    g_is_i32;              // edge_index dtype flag

__device__ __forceinline__ float group4_sum(float v) {
    v += __shfl_xor_sync(0xffffffffu, v, 1);
    v += __shfl_xor_sync(0xffffffffu, v, 2);
    return v;
}

__device__ __forceinline__ int load_idx(const void* ei, long long off) {
    if (g_is_i32) return ((const int*)ei)[off];
    return (int)((const long long*)ei)[off];
}

// ---- preprocessing: dtype detect + counting sort of edges by target ----

// Fused: zero the count array; block 0 / warp 0 also detects index dtype
// (int64 nonneg values < 2^31 have zero high words).
__global__ void zero_detect_kernel(const unsigned int* __restrict__ w) {
    int i = blockIdx.x * blockDim.x + threadIdx.x;
    if (i <= kNodes) g_count[i] = 0;
    if (blockIdx.x == 0 && threadIdx.x < 32) {
        unsigned int acc = 0;
        for (int k = threadIdx.x; k < 1024; k += 32) acc |= w[2 * k + 1];
        #pragma unroll
        for (int d = 1; d < 32; d <<= 1) acc |= __shfl_xor_sync(0xffffffffu, acc, d);
        if (threadIdx.x == 0) g_is_i32 = (acc != 0) ? 1 : 0;
    }
}

__global__ void hist_kernel(const void* __restrict__ ei) {
    int e = blockIdx.x * blockDim.x + threadIdx.x;
    if (e >= kEdges) return;
    atomicAdd(&g_count[load_idx(ei, (long long)kEdges + e)], 1);
}

// S1: per-block inclusive scan of counts (256/block) + block totals.
__global__ void __launch_bounds__(256) scan1_kernel() {
    __shared__ int warp_tot[8];
    int i    = blockIdx.x * 256 + threadIdx.x;
    int lane = threadIdx.x & 31;
    int wid  = threadIdx.x >> 5;

    int v = (i < kNodes) ? g_count[i] : 0;
    int x = v;
    #pragma unroll
    for (int d = 1; d < 32; d <<= 1) {
        int y = __shfl_up_sync(0xffffffffu, x, d);
        if (lane >= d) x += y;
    }
    if (lane == 31) warp_tot[wid] = x;
    __syncthreads();
    if (wid == 0) {
        int t = (lane < 8) ? warp_tot[lane] : 0;
        #pragma unroll
        for (int d = 1; d < 8; d <<= 1) {
            int y = __shfl_up_sync(0xffffffffu, t, d);
            if (lane >= d) t += y;
        }
        if (lane < 8) warp_tot[lane] = t;
    }
    __syncthreads();
    int incl = x + (wid > 0 ? warp_tot[wid - 1] : 0);
    if (i < kNodes) g_incl[i] = incl;
    if (threadIdx.x == 255) g_bsum[blockIdx.x] = incl;
}

// S2: exclusive scan of 196 block totals (single tiny block).
__global__ void __launch_bounds__(256) scan2_kernel() {
    __shared__ int warp_tot[8];
    int lane = threadIdx.x & 31;
    int wid  = threadIdx.x >> 5;
    int v = (threadIdx.x < kScanBlocks) ? g_bsum[threadIdx.x] : 0;
    int x = v;
    #pragma unroll
    for (int d = 1; d < 32; d <<= 1) {
        int y = __shfl_up_sync(0xffffffffu, x, d);
        if (lane >= d) x += y;
    }
    if (lane == 31) warp_tot[wid] = x;
    __syncthreads();
    if (wid == 0) {
        int t = (lane < 8) ? warp_tot[lane] : 0;
        #pragma unroll
        for (int d = 1; d < 8; d <<= 1) {
            int y = __shfl_up_sync(0xffffffffu, t, d);
            if (lane >= d) t += y;
        }
        if (lane < 8) warp_tot[lane] = t;
    }
    __syncthreads();
    int incl = x + (wid > 0 ? warp_tot[wid - 1] : 0);
    if (threadIdx.x < kScanBlocks) g_bpre[threadIdx.x] = incl - v;  // exclusive
}

// S3: offs[i] = bpre[blk] + incl[i] - count[i]; cursor = offs; offs[N] = E.
__global__ void __launch_bounds__(256) scan3_kernel() {
    int i = blockIdx.x * 256 + threadIdx.x;
    if (i < kNodes) {
        int off = g_bpre[blockIdx.x] + g_incl[i] - g_count[i];
        g_offs[i]   = off;
        g_cursor[i] = off;
    }
    if (i == 0) g_offs[kNodes] = kEdges;
}

__global__ void scatter_kernel(const void* __restrict__ ei) {
    int e = blockIdx.x * blockDim.x + threadIdx.x;
    if (e >= kEdges) return;
    int s = load_idx(ei, e);
    int g = load_idx(ei, (long long)kEdges + e);
    int pos = atomicAdd(&g_cursor[g], 1);
    g_srcs[pos] = s;
}

// ---- compute ----

// xc = l2norm_per_capsule(x). One warp per node, float4 per lane.
__global__ void __launch_bounds__(256) init_kernel(const float* __restrict__ x) {
    int gid  = blockIdx.x * blockDim.x + threadIdx.x;
    int node = gid >> 5;
    if (node >= kNodes) return;
    int t   = gid & 31;
    int idx = node * 32 + t;

    float4 v = reinterpret_cast<const float4*>(x)[idx];
    float ss = group4_sum(v.x * v.x + v.y * v.y + v.z * v.z + v.w * v.w);
    float s  = 1.0f / fmaxf(sqrtf(ss), 1e-12f);
    v.x *= s; v.y *= s; v.z *= s; v.w *= s;
    g_xc[idx] = v;
}

// One routing iteration, HALF-WARP per node: warp w owns nodes {2w, 2w+1}.
// Lane h in [0,16) of each half owns dims [8h, 8h+8); capsule c = h>>1.
// Per loop iteration the warp retires 2 edges (one per half) with one
// instruction stream -> ~2x issue efficiency vs warp-per-edge-row.
// Softmax reductions: xor1 (capsule dot), xor{2,4,8} (8-cap sum) — all
// confined to the half-warp automatically. No max-subtract needed
// (capsules are unit vectors => p in [-1,1]).
template <bool FIRST, bool WRITE_OUT>
__global__ void __launch_bounds__(256) route_kernel(float* __restrict__ out) {
    int gid  = blockIdx.x * blockDim.x + threadIdx.x;
    int lane = threadIdx.x & 31;
    int h    = lane & 15;
    int node = (gid >> 5) * 2 + (lane >> 4);   // kNodes even; grid sized exactly

    // u (and residual c) slice: 8 floats = 2 float4s at float4-index node*32 + h*2.
    const float4* ub = (FIRST ? g_xc : g_u) + node * 32 + h * 2;
    float4 ua = ub[0];
    float4 uc = ub[1];

    int beg  = g_offs[node];
    int deg  = g_offs[node + 1] - beg;
    int safe = min(beg, kEdges - 1);
    int degO = __shfl_xor_sync(0xffffffffu, deg, 16);
    int jmax = max(deg, degO);

    float4 aA = make_float4(0.f, 0.f, 0.f, 0.f);
    float4 aB = make_float4(0.f, 0.f, 0.f, 0.f);

    for (int j = 0; j < jmax; ++j) {
        bool valid = j < deg;                 // uniform within each half-warp
        int  s     = g_srcs[valid ? beg + j : safe];

        const float4* zb = g_xc + s * 32 + h * 2;
        float4 zA = zb[0];
        float4 zB = zb[1];

        float d = zA.x * ua.x + zA.y * ua.y + zA.z * ua.z + zA.w * ua.w
                + zB.x * uc.x + zB.y * uc.y + zB.z * uc.z + zB.w * uc.w;
        d += __shfl_xor_sync(0xffffffffu, d, 1);      // capsule dot (2 lanes/cap)

        float e = __expf(d);
        float q = e;
        q += __shfl_xor_sync(0xffffffffu, q, 2);
        q += __shfl_xor_sync(0xffffffffu, q, 4);
        q += __shfl_xor_sync(0xffffffffu, q, 8);      // sum over 8 capsules
        float w = valid ? __fdividef(e, q) : 0.f;

        aA.x += zA.x * w; aA.y += zA.y * w; aA.z += zA.z * w; aA.w += zA.w * w;
        aB.x += zB.x * w; aB.y += zB.y * w; aB.z += zB.z * w; aB.w += zB.w * w;
    }

    // Residual + per-capsule l2norm. For FIRST, c == u already in registers.
    float4 cA, cB;
    if (FIRST) { cA = ua; cB = uc; }
    else {
        const float4* cb = g_xc + node * 32 + h * 2;
        cA = cb[0]; cB = cb[1];
    }
    float4 vA = make_float4(aA.x + cA.x, aA.y + cA.y, aA.z + cA.z, aA.w + cA.w);
    float4 vB = make_float4(aB.x + cB.x, aB.y + cB.y, aB.z + cB.z, aB.w + cB.w);

    float ss = vA.x * vA.x + vA.y * vA.y + vA.z * vA.z + vA.w * vA.w
             + vB.x * vB.x + vB.y * vB.y + vB.z * vB.z + vB.w * vB.w;
    ss += __shfl_xor_sync(0xffffffffu, ss, 1);        // capsule sum-of-squares
    float sc = 1.0f / fmaxf(sqrtf(ss), 1e-12f);

    float4* dst = (WRITE_OUT ? reinterpret_cast<float4*>(out) : g_u) + node * 32 + h * 2;
    dst[0] = make_float4(vA.x * sc, vA.y * sc, vA.z * sc, vA.w * sc);
    dst[1] = make_float4(vB.x * sc, vB.y * sc, vB.z * sc, vB.w * sc);
}

}  // namespace

extern "C" void kernel_launch(void* const* d_in, const int* in_sizes, int n_in,
                              void* d_out, int out_size) {
    const float* x  = (const float*)d_in[0];
    const void*  ei = d_in[1];   // [2, E], int32 or int64 (detected on-device)
    float* out = (float*)d_out;

    const int nodeBlocks  = (kNodes * 32 + 255) / 256;       // warp per node
    const int pairBlocks  = (kNodes / 2 * 32 + 255) / 256;   // warp per node-pair
    const int edgeBlocks  = (kEdges + 255) / 256;

    zero_detect_kernel<<<(kNodes + 256) / 256, 256>>>((const unsigned int*)ei);
    hist_kernel<<<edgeBlocks, 256>>>(ei);
    scan1_kernel<<<kScanBlocks, 256>>>();
    scan2_kernel<<<1, 256>>>();
    scan3_kernel<<<kScanBlocks, 256>>>();
    scatter_kernel<<<edgeBlocks, 256>>>(ei);
    init_kernel<<<nodeBlocks, 256>>>(x);

    route_kernel<true,  false><<<pairBlocks, 256>>>(nullptr);
    route_kernel<false, false><<<pairBlocks, 256>>>(nullptr);
    route_kernel<false, true ><<<pairBlocks, 256>>>(out);
}